// round 1
// baseline (speedup 1.0000x reference)
#include <cuda_runtime.h>

// Problem constants (from setup_inputs): B=4, C=3, H=W=384, F=5
#define BB 4
#define CC 3
#define HH 384
#define WW 384
#define FF 5
#define KK (FF * FF)
#define HW (HH * WW)

__global__ __launch_bounds__(256) void dsepconv_kernel(
    const float* __restrict__ inp,    // [B, C, H, W]
    const float* __restrict__ vert,   // [B, F, H, W]
    const float* __restrict__ horiz,  // [B, F, H, W]
    const float* __restrict__ offx,   // [B, FF, H, W]
    const float* __restrict__ offy,   // [B, FF, H, W]
    const float* __restrict__ mask,   // [B, FF, H, W]
    float* __restrict__ out)          // [B, C, H, W]
{
    int idx = blockIdx.x * blockDim.x + threadIdx.x;
    if (idx >= BB * HW) return;

    const int w = idx % WW;
    const int h = (idx / WW) % HH;
    const int b = idx / HW;
    const int phw = h * WW + w;

    const float* inb = inp + b * (CC * HW);

    // Per-pixel separable filter taps (reused across all 25 k's)
    float v[FF], hz[FF];
#pragma unroll
    for (int i = 0; i < FF; i++) {
        v[i]  = vert [(b * FF + i) * HW + phw];
        hz[i] = horiz[(b * FF + i) * HW + phw];
    }

    const float* ox_p = offx + b * (KK * HW) + phw;
    const float* oy_p = offy + b * (KK * HW) + phw;
    const float* m_p  = mask + b * (KK * HW) + phw;

    float acc0 = 0.f, acc1 = 0.f, acc2 = 0.f;

#pragma unroll
    for (int k = 0; k < KK; k++) {
        const int ki = k / FF;
        const int kj = k % FF;

        const float ox = ox_p[k * HW];
        const float oy = oy_p[k * HW];
        const float m  = m_p [k * HW];

        const float wt = v[ki] * hz[kj] * m;

        float py = oy + (float)(h + ki - 2);
        float px = ox + (float)(w + kj - 2);
        py = fminf(fmaxf(py, 0.f), (float)(HH - 1));
        px = fminf(fmaxf(px, 0.f), (float)(WW - 1));

        const float y0f = floorf(py);
        const float x0f = floorf(px);
        const float wy = py - y0f;
        const float wx = px - x0f;

        const int y0 = (int)y0f;
        const int x0 = (int)x0f;
        const int y1 = min(y0 + 1, HH - 1);
        const int x1 = min(x0 + 1, WW - 1);

        const int i00 = y0 * WW + x0;
        const int i01 = y0 * WW + x1;
        const int i10 = y1 * WW + x0;
        const int i11 = y1 * WW + x1;

        const float w00 = (1.f - wy) * (1.f - wx);
        const float w01 = (1.f - wy) * wx;
        const float w10 = wy * (1.f - wx);
        const float w11 = wy * wx;

        // Channel 0
        {
            const float* p = inb;
            float s = p[i00] * w00 + p[i01] * w01 + p[i10] * w10 + p[i11] * w11;
            acc0 = fmaf(wt, s, acc0);
        }
        // Channel 1
        {
            const float* p = inb + HW;
            float s = p[i00] * w00 + p[i01] * w01 + p[i10] * w10 + p[i11] * w11;
            acc1 = fmaf(wt, s, acc1);
        }
        // Channel 2
        {
            const float* p = inb + 2 * HW;
            float s = p[i00] * w00 + p[i01] * w01 + p[i10] * w10 + p[i11] * w11;
            acc2 = fmaf(wt, s, acc2);
        }
    }

    float* ob = out + b * (CC * HW) + phw;
    ob[0]      = acc0;
    ob[HW]     = acc1;
    ob[2 * HW] = acc2;
}

extern "C" void kernel_launch(void* const* d_in, const int* in_sizes, int n_in,
                              void* d_out, int out_size)
{
    const float* inp   = (const float*)d_in[0];
    const float* vert  = (const float*)d_in[1];
    const float* horiz = (const float*)d_in[2];
    const float* offx  = (const float*)d_in[3];
    const float* offy  = (const float*)d_in[4];
    const float* mask  = (const float*)d_in[5];
    float* out = (float*)d_out;

    const int n = BB * HW;  // one thread per (b,h,w)
    const int threads = 256;
    const int blocks = (n + threads - 1) / threads;
    dsepconv_kernel<<<blocks, threads>>>(inp, vert, horiz, offx, offy, mask, out);
}

// round 2
// speedup vs baseline: 1.1184x; 1.1184x over previous
#include <cuda_runtime.h>

// Problem constants: B=4, C=3, H=W=384, F=5
#define BB 4
#define CC 3
#define HH 384
#define WW 384
#define FF 5
#define KK (FF * FF)
#define HW (HH * WW)

// Tile config: 32x8 pixels per block (256 threads), halo 8 on each side.
#define TX 32
#define TY 8
#define HALO 8
#define TW (TX + 2 * HALO)   // 48
#define TH (TY + 2 * HALO)   // 24
#define TSZ (TW * TH)        // 1152 floats per channel

__global__ __launch_bounds__(256) void dsepconv_tile_kernel(
    const float* __restrict__ inp,    // [B, C, H, W]
    const float* __restrict__ vert,   // [B, F, H, W]
    const float* __restrict__ horiz,  // [B, F, H, W]
    const float* __restrict__ offx,   // [B, FF, H, W]
    const float* __restrict__ offy,   // [B, FF, H, W]
    const float* __restrict__ mask,   // [B, FF, H, W]
    float* __restrict__ out)          // [B, C, H, W]
{
    __shared__ float tile[CC * TSZ];

    const int b   = blockIdx.z;
    const int bx  = blockIdx.x * TX;     // tile origin (pixel coords)
    const int by  = blockIdx.y * TY;
    const int ox0 = bx - HALO;           // smem tile origin (global coords)
    const int oy0 = by - HALO;

    const float* inb = inp + b * (CC * HW);

    // Cooperative tile load with clamp-to-edge (replicates the reference's
    // coordinate clipping semantics for rows/cols just past the image edge).
    for (int i = threadIdx.x; i < TSZ; i += 256) {
        const int r = i / TW;
        const int c = i - r * TW;
        const int gy = min(max(oy0 + r, 0), HH - 1);
        const int gx = min(max(ox0 + c, 0), WW - 1);
        const int g = gy * WW + gx;
        tile[i]           = inb[g];
        tile[TSZ + i]     = inb[HW + g];
        tile[2 * TSZ + i] = inb[2 * HW + g];
    }
    __syncthreads();

    const int tx = threadIdx.x & 31;
    const int ty = threadIdx.x >> 5;
    const int w  = bx + tx;
    const int h  = by + ty;
    const int phw = h * WW + w;

    // Separable filter taps for this pixel (reused across all 25 k's)
    float v[FF], hz[FF];
#pragma unroll
    for (int i = 0; i < FF; i++) {
        v[i]  = vert [(b * FF + i) * HW + phw];
        hz[i] = horiz[(b * FF + i) * HW + phw];
    }

    const float* ox_p = offx + b * (KK * HW) + phw;
    const float* oy_p = offy + b * (KK * HW) + phw;
    const float* m_p  = mask + b * (KK * HW) + phw;

    float acc0 = 0.f, acc1 = 0.f, acc2 = 0.f;

#pragma unroll
    for (int k = 0; k < KK; k++) {
        const int ki = k / FF;
        const int kj = k % FF;

        const float oy = oy_p[k * HW];
        const float ox = ox_p[k * HW];
        const float m  = m_p [k * HW];

        const float wt = v[ki] * hz[kj] * m;

        float py = oy + (float)(h + ki - 2);
        float px = ox + (float)(w + kj - 2);
        py = fminf(fmaxf(py, 0.f), (float)(HH - 1));
        px = fminf(fmaxf(px, 0.f), (float)(WW - 1));

        const float y0f = floorf(py);
        const float x0f = floorf(px);
        const float wy = py - y0f;
        const float wx = px - x0f;

        const int y0 = (int)y0f;
        const int x0 = (int)x0f;

        const float w00 = (1.f - wy) * (1.f - wx);
        const float w01 = (1.f - wy) * wx;
        const float w10 = wy * (1.f - wx);
        const float w11 = wy * wx;

        const unsigned ly = (unsigned)(y0 - oy0);
        const unsigned lx = (unsigned)(x0 - ox0);

        if (ly < (TH - 1) && lx < (TW - 1)) {
            // Fast path: all 4 corners (incl. the +1 bilinear neighbors, which
            // the clamped tile-load already replicated at image edges) in smem.
            const float* t = tile + ly * TW + lx;
            float s0 = t[0] * w00 + t[1] * w01 + t[TW] * w10 + t[TW + 1] * w11;
            acc0 = fmaf(wt, s0, acc0);
            t += TSZ;
            float s1 = t[0] * w00 + t[1] * w01 + t[TW] * w10 + t[TW + 1] * w11;
            acc1 = fmaf(wt, s1, acc1);
            t += TSZ;
            float s2 = t[0] * w00 + t[1] * w01 + t[TW] * w10 + t[TW + 1] * w11;
            acc2 = fmaf(wt, s2, acc2);
        } else {
            // Rare path (|offset| > ~5 sigma): gather from global.
            const int y1 = min(y0 + 1, HH - 1);
            const int x1 = min(x0 + 1, WW - 1);
            const int i00 = y0 * WW + x0;
            const int i01 = y0 * WW + x1;
            const int i10 = y1 * WW + x0;
            const int i11 = y1 * WW + x1;
            {
                const float* p = inb;
                float s = p[i00] * w00 + p[i01] * w01 + p[i10] * w10 + p[i11] * w11;
                acc0 = fmaf(wt, s, acc0);
            }
            {
                const float* p = inb + HW;
                float s = p[i00] * w00 + p[i01] * w01 + p[i10] * w10 + p[i11] * w11;
                acc1 = fmaf(wt, s, acc1);
            }
            {
                const float* p = inb + 2 * HW;
                float s = p[i00] * w00 + p[i01] * w01 + p[i10] * w10 + p[i11] * w11;
                acc2 = fmaf(wt, s, acc2);
            }
        }
    }

    float* ob = out + b * (CC * HW) + phw;
    ob[0]      = acc0;
    ob[HW]     = acc1;
    ob[2 * HW] = acc2;
}

extern "C" void kernel_launch(void* const* d_in, const int* in_sizes, int n_in,
                              void* d_out, int out_size)
{
    const float* inp   = (const float*)d_in[0];
    const float* vert  = (const float*)d_in[1];
    const float* horiz = (const float*)d_in[2];
    const float* offx  = (const float*)d_in[3];
    const float* offy  = (const float*)d_in[4];
    const float* mask  = (const float*)d_in[5];
    float* out = (float*)d_out;

    dim3 grid(WW / TX, HH / TY, BB);   // 12 x 48 x 4
    dsepconv_tile_kernel<<<grid, 256>>>(inp, vert, horiz, offx, offy, mask, out);
}